// round 15
// baseline (speedup 1.0000x reference)
#include <cuda_runtime.h>
#include <cuda_bf16.h>
#include <math.h>

// Problem constants
#define BB    512
#define SS    256
#define IDIM  32
#define HH    256
#define OO    24

// Geometry
#define CL     8                  // CTAs per cluster
#define ROWS   32                 // batch rows per cluster
#define NCLU   (BB/ROWS)          // 16 clusters
#define GRID_R (NCLU*CL)          // 128 CTAs
#define NTHR   256                // 8 warps, all GEMM (n-split: 32m x 16n each)
#define NCH    18                 // 18 k16 chunks (k 0..287)

#define ASTRIDE 592               // A bytes per m-row (576 + 16 pad)
#define A_BYTES (128*ASTRIDE)     // 75776 per precision

// B layout: [k][n] n-contiguous. 9 blocks of 4KB per parity:
//   block b (b=0..7: h rows k=b*32..+32; b=8: x rows k=256..287)
//   block = [hi: 32 rows x 64B][lo: 32 rows x 64B]
#define BPARN  36864              // 9 * 4096 bytes per parity

// SMEM offsets (bytes)
#define A_HI   0
#define A_LO   75776
#define BOFF   151552             // B[p] at BOFF + p*BPARN
#define MB_FULL0  (BOFF + 2*BPARN)   // 225280: full0 @+0, full1 @+8
#define MB_EMPTY0 (MB_FULL0 + 16)    // empty0 @+16, empty1 @+24
#define SMEM_BYTES (MB_FULL0 + 64)   // 225344

#define H_TX_BYTES (7u*4096u)     // 7 peer bulk copies of 4KB

// Device scratch
__device__ __align__(16) unsigned char g_Ahi[CL*A_BYTES];
__device__ __align__(16) unsigned char g_Alo[CL*A_BYTES];
__device__ float g_bc[CL*128];    // composed bias [rank][m = c*4+q]
__device__ float g_hfinal[BB*HH];

typedef unsigned long long u64;

// ---------------- helpers ----------------
__device__ __forceinline__ unsigned s2u(const void *p) {
    unsigned r;
    asm("{.reg .u64 t; cvta.to.shared.u64 t,%1; cvt.u32.u64 %0,t;}" : "=r"(r) : "l"(p));
    return r;
}
__device__ __forceinline__ unsigned mapa_sh(unsigned a, unsigned r) {
    unsigned o; asm("mapa.shared::cluster.u32 %0,%1,%2;" : "=r"(o) : "r"(a), "r"(r)); return o;
}
__device__ __forceinline__ void carr() { asm volatile("barrier.cluster.arrive.aligned;" ::: "memory"); }
__device__ __forceinline__ void cwait(){ asm volatile("barrier.cluster.wait.aligned;"   ::: "memory"); }
__device__ __forceinline__ void csync(){ carr(); cwait(); }
__device__ __forceinline__ void fence_pa() { asm volatile("fence.proxy.async.shared::cta;" ::: "memory"); }

__device__ __forceinline__ void mbar_init(unsigned a, unsigned cnt) {
    asm volatile("mbarrier.init.shared.b64 [%0], %1;" :: "r"(a), "r"(cnt) : "memory");
}
__device__ __forceinline__ void mbar_expect_tx(unsigned a, unsigned bytes) {
    asm volatile("mbarrier.arrive.expect_tx.shared.b64 _, [%0], %1;" :: "r"(a), "r"(bytes) : "memory");
}
__device__ __forceinline__ void mbar_arrive_remote(unsigned a) {
    asm volatile("mbarrier.arrive.release.cluster.shared::cluster.b64 _, [%0];" :: "r"(a) : "memory");
}
__device__ __forceinline__ void mbar_wait(unsigned a, unsigned parity) {
    asm volatile(
        "{.reg .pred P1;\n\t"
        "WL%=: mbarrier.try_wait.parity.acquire.cta.shared::cta.b64 P1, [%0], %1, 0x989680;\n\t"
        "@P1 bra.uni WD%=;\n\t"
        "bra.uni WL%=;\n\t"
        "WD%=:}" :: "r"(a), "r"(parity) : "memory");
}
// bulk DSMEM copy local smem -> peer smem, counts bytes on peer's mbarrier
__device__ __forceinline__ void bulk_s2s(unsigned dst, unsigned src, unsigned bytes, unsigned mb) {
    asm volatile("cp.async.bulk.shared::cluster.shared::cta.mbarrier::complete_tx::bytes [%0], [%1], %2, [%3];"
                 :: "r"(dst), "r"(src), "r"(bytes), "r"(mb) : "memory");
}

__device__ __forceinline__ void ldm4(unsigned* r, unsigned a) {
    asm volatile("ldmatrix.sync.aligned.m8n8.x4.shared.b16 {%0,%1,%2,%3},[%4];"
        : "=r"(r[0]), "=r"(r[1]), "=r"(r[2]), "=r"(r[3]) : "r"(a));
}
__device__ __forceinline__ void ldm4t(unsigned* r, unsigned a) {
    asm volatile("ldmatrix.sync.aligned.m8n8.x4.trans.shared.b16 {%0,%1,%2,%3},[%4];"
        : "=r"(r[0]), "=r"(r[1]), "=r"(r[2]), "=r"(r[3]) : "r"(a));
}
__device__ __forceinline__ void mma16816(float* d, const unsigned* a, unsigned b0, unsigned b1) {
    asm volatile("mma.sync.aligned.m16n8k16.row.col.f32.bf16.bf16.f32 "
        "{%0,%1,%2,%3},{%4,%5,%6,%7},{%8,%9},{%0,%1,%2,%3};"
        : "+f"(d[0]), "+f"(d[1]), "+f"(d[2]), "+f"(d[3])
        : "r"(a[0]), "r"(a[1]), "r"(a[2]), "r"(a[3]), "r"(b0), "r"(b1));
}

__device__ __forceinline__ float fast_tanh(float x) {
    return 1.f - __fdividef(2.f, __expf(2.f*x) + 1.f);
}
__device__ __forceinline__ void split1(float v, unsigned short &h, unsigned short &l) {
    __nv_bfloat16 bh = __float2bfloat16(v);
    h = __bfloat16_as_ushort(bh);
    l = __bfloat16_as_ushort(__float2bfloat16(v - __bfloat162float(bh)));
}

// ---------------------------------------------------------------------------
// prep: bf16 hi/lo weight images [rank][m][k], m = c*4+q <-> gate g = q*256+rank*32+c
// ---------------------------------------------------------------------------
__global__ void prep_kernel(const float* __restrict__ W, const float* __restrict__ R,
                            const float* __restrict__ b, const float* __restrict__ b_in,
                            const float* __restrict__ W_in)
{
    int idx = blockIdx.x * blockDim.x + threadIdx.x;
    if (idx < CL*128*296) {
        int kk   = idx % 296;
        int m    = (idx / 296) % 128;
        int rank = idx / (296*128);
        int c = m >> 2, q = m & 3;
        int g = q*256 + rank*32 + c;
        float w = 0.f;
        if (kk < 256) {
            w = W[(size_t)g*512 + 256 + kk] + R[(size_t)g*256 + kk];
        } else if (kk < 288) {
            int i = kk - 256;
            float s = 0.f;
            for (int h = 0; h < HH; ++h) s += W[(size_t)g*512 + h] * W_in[(size_t)h*IDIM + i];
            w = s;
        }
        __nv_bfloat16 hi = __float2bfloat16(w);
        __nv_bfloat16 lo = __float2bfloat16(w - __bfloat162float(hi));
        size_t off = (size_t)rank*A_BYTES + (size_t)m*ASTRIDE + kk*2;
        *(__nv_bfloat16*)(g_Ahi + off) = hi;
        *(__nv_bfloat16*)(g_Alo + off) = lo;
    }
    if (idx < CL*128) {
        int m = idx & 127, rank = idx >> 7;
        int c = m >> 2, q = m & 3;
        int g = q*256 + rank*32 + c;
        float s = b[g];
        for (int h = 0; h < HH; ++h) s += W[(size_t)g*512 + h] * b_in[h];
        g_bc[idx] = s;
    }
}

__global__ void dummy_kernel() {}

// ---------------------------------------------------------------------------
// Recurrence: HMMA 3-term hi/lo; 8 warps n-split (R12 compute). h exchange via
// 7 cp.async.bulk (4KB each) + tx-counting mbarriers. B is [k][n]-major, so
// each CTA's h slice is one contiguous 4KB block. No cluster barrier in loop.
// ---------------------------------------------------------------------------
__global__ void __cluster_dims__(CL, 1, 1) __launch_bounds__(NTHR, 1)
recur_kernel(const float* __restrict__ x)
{
    extern __shared__ unsigned char smem[];
    const unsigned base = s2u(smem);

    unsigned rank; asm("mov.u32 %0, %%cluster_ctarank;" : "=r"(rank));
    const int cid  = blockIdx.x >> 3;
    const int b0   = cid * ROWS;
    const int tid  = threadIdx.x;
    const int lane = tid & 31;
    const int warp = tid >> 5;
    const int kh   = warp >> 2;    // batch-row half
    const int wm   = warp & 3;     // m-tile

    // ---- mbarrier init ----
    if (tid == 0) {
        mbar_init(base + MB_FULL0,      1);
        mbar_init(base + MB_FULL0 + 8,  1);
        mbar_init(base + MB_EMPTY0,     CL);
        mbar_init(base + MB_EMPTY0 + 8, CL);
        asm volatile("fence.mbarrier_init.release.cluster;" ::: "memory");
    }

    // ---- load resident A tiles; zero B parity-0 ----
    {
        const float4* sa = (const float4*)(g_Ahi + (size_t)rank*A_BYTES);
        const float4* sb = (const float4*)(g_Alo + (size_t)rank*A_BYTES);
        float4* da = (float4*)(smem + A_HI);
        float4* db = (float4*)(smem + A_LO);
        for (int i = tid; i < A_BYTES/16; i += NTHR) { da[i] = sa[i]; db[i] = sb[i]; }
        float4 z = make_float4(0.f,0.f,0.f,0.f);
        float4* bz = (float4*)(smem + BOFF);
        for (int i = tid; i < BPARN/16; i += NTHR) bz[i] = z;
    }
    __syncthreads();

    // ---- x staging plumbing: n_s = tid>>3, 4 features at f_s ----
    const int n_s = tid >> 3;
    const int f_s = (tid & 7) * 4;
    const float* xrb = x + (size_t)(b0 + n_s)*SS*IDIM + f_s;
    // x block = block 8 of parity region: addr = 8*4096 + feat*64 + n*2 (hi), +2048 (lo)
    const unsigned xob = 8u*4096u + (unsigned)f_s*64u + (unsigned)n_s*2u;

    {   // stage x(0) into parity 0
        float4 a0 = *(const float4*)(xrb);
        unsigned char* dst = smem + BOFF + xob;
        const float vv[4] = {a0.x, a0.y, a0.z, a0.w};
        #pragma unroll
        for (int i = 0; i < 4; ++i) {
            unsigned short hb, lb; split1(vv[i], hb, lb);
            *(unsigned short*)(dst + i*64)        = hb;
            *(unsigned short*)(dst + i*64 + 2048) = lb;
        }
    }
    __syncthreads();
    csync();          // B(0) + mbar inits visible cluster-wide

    // ---- GEMM lane addressing ----
    // A: [m][k] unchanged
    const unsigned aH  = base + A_HI + (unsigned)(wm*32 + (lane & 15))*ASTRIDE + (lane >> 4)*16;
    const unsigned aL  = aH + (A_LO - A_HI);
    // B: [k][n], ldmatrix.trans. lane = g*8+j: k_local = (g>>1)*8+j, n = kh*16+(g&1)*8
    const int gB = lane >> 3, jB = lane & 7;
    const unsigned laneB = (unsigned)(((gB >> 1)*8 + jB)*64) + (unsigned)((kh*16 + (gB & 1)*8)*2);
    const unsigned bB = base + BOFF + laneB;   // + p*BPARN + bOff(ch); lo at +2048

    const int r   = lane >> 2;     // 0..7
    const int qt  = lane & 3;
    const int s2  = r & 3;
    const int rb  = r >> 2;

    const int n_e = kh*16 + (s2 >> 1)*8 + qt*2 + (s2 & 1);
    float bias[4][4];
    float cst[4], nst[4], mst[4];
    #pragma unroll
    for (int k = 0; k < 4; ++k)
        #pragma unroll
        for (int j = 0; j < 4; ++j)
            bias[j][k] = g_bc[rank*128 + (wm*8 + 2*k + rb)*4 + j];
    #pragma unroll
    for (int u = 0; u < 4; ++u) { cst[u]=0.f; nst[u]=0.f; mst[u]=0.f; }

    // staging base for this thread's h values (within a parity region):
    // block rank, row c_local = wm*8+2k+rb, col n_e
    const unsigned hob = (unsigned)rank*4096u + (unsigned)((wm*8 + rb)*64) + (unsigned)(n_e*2);

    float* ghf = g_hfinal + (size_t)(b0 + n_e)*HH + rank*32 + wm*8 + rb;

    for (int t = 0; t < SS; ++t) {
        const unsigned p  = (unsigned)(t & 1);
        const unsigned p1 = p ^ 1u;
        const int ph = ((t - 2 + (t & 1)) >> 1) & 1;   // shared parity for waits

        // prefetch x(t+1)
        float4 xv;
        if (t + 1 < SS) xv = *(const float4*)(xrb + (size_t)(t+1)*IDIM);

        // wait inbound h for step t (7 bulk copies -> full[p])
        if (t > 0) mbar_wait(base + MB_FULL0 + p*8, (unsigned)ph);

        // ---- GEMM: 32m x 16n x 288k, 3-term hi/lo ----
        float d[2][2][4];
        #pragma unroll
        for (int mi = 0; mi < 2; ++mi)
            #pragma unroll
            for (int nj = 0; nj < 2; ++nj)
                #pragma unroll
                for (int e = 0; e < 4; ++e) d[mi][nj][e] = 0.f;

        const unsigned bP = bB + p*BPARN;
        #pragma unroll 6
        for (int ch = 0; ch < NCH; ++ch) {
            unsigned bo = (unsigned)((ch >> 1)*4096 + (ch & 1)*1024);
            unsigned ka = (unsigned)ch*32;
            unsigned AH0[4], AH1[4], AL0[4], AL1[4], BH[4], BL[4];
            ldm4(AH0, aH + ka); ldm4(AH1, aH + 16*ASTRIDE + ka);
            ldm4(AL0, aL + ka); ldm4(AL1, aL + 16*ASTRIDE + ka);
            ldm4t(BH, bP + bo); ldm4t(BL, bP + bo + 2048);
            #pragma unroll
            for (int nj = 0; nj < 2; ++nj) {
                mma16816(d[0][nj], AH0, BH[nj], BH[nj+2]);
                mma16816(d[0][nj], AL0, BH[nj], BH[nj+2]);
                mma16816(d[0][nj], AH0, BL[nj], BL[nj+2]);
                mma16816(d[1][nj], AH1, BH[nj], BH[nj+2]);
                mma16816(d[1][nj], AL1, BH[nj], BH[nj+2]);
                mma16816(d[1][nj], AH1, BL[nj], BL[nj+2]);
            }
        }

        __syncthreads();   // all local reads of B[p] complete

        if (tid == 0 && t + 1 < SS) {
            // notify all CTAs: done reading B[p]
            unsigned emb = base + MB_EMPTY0 + p*8;
            #pragma unroll
            for (unsigned rr = 0; rr < CL; ++rr)
                mbar_arrive_remote(mapa_sh(emb, rr));
            // arm full[p1] for next inbound round
            mbar_expect_tx(base + MB_FULL0 + p1*8, H_TX_BYTES);
        }

        // ---- 4x4 transpose: gates (lane bits 2-3) <-> cols (nj,np) ----
        float v[4][4];
        #pragma unroll
        for (int mi = 0; mi < 2; ++mi)
            #pragma unroll
            for (int nj = 0; nj < 2; ++nj)
                #pragma unroll
                for (int e = 0; e < 4; ++e)
                    v[nj*2 + (e & 1)][2*mi + (e >> 1)] = d[mi][nj][e];

        float t1[4][4], g[4][4];
        #pragma unroll
        for (int j = 0; j < 4; ++j) {
            bool sw = ((s2 ^ j) & 1) != 0;
            #pragma unroll
            for (int k = 0; k < 4; ++k) {
                float ov = __shfl_xor_sync(0xffffffffu, v[j^1][k], 4);
                t1[j][k] = sw ? ov : v[j][k];
            }
        }
        #pragma unroll
        for (int j = 0; j < 4; ++j) {
            bool sw = ((s2 ^ j) & 2) != 0;
            #pragma unroll
            for (int k = 0; k < 4; ++k) {
                float ov = __shfl_xor_sync(0xffffffffu, t1[j^2][k], 8);
                g[j][k] = sw ? ov : t1[j][k];
            }
        }

        // ---- pointwise sLSTM (4 cells) + staging / final store ----
        unsigned char* stg = smem + BOFF + p1*BPARN + hob;
        #pragma unroll
        for (int k = 0; k < 4; ++k) {
            float gi = g[0][k] + bias[0][k];
            float gf = g[1][k] + bias[1][k];
            float gz = g[2][k] + bias[2][k];
            float go = g[3][k] + bias[3][k];
            float lf  = -__logf(1.f + __expf(-gf));
            float mn  = fmaxf(lf + mst[k], gi);
            float ipr = __expf(gi - mn);
            float fp  = __expf(lf + mst[k] - mn);
            float cn  = fp*cst[k] + ipr*fast_tanh(gz);
            float nn  = fp*nst[k] + ipr;
            float so  = __fdividef(1.f, 1.f + __expf(-go));
            float hv  = so * fast_tanh(__fdividef(cn, nn));
            cst[k]=cn; nst[k]=nn; mst[k]=mn;
            if (t + 1 < SS) {
                unsigned short hb, lb; split1(hv, hb, lb);
                *(unsigned short*)(stg + k*128)        = hb;   // row c=wm*8+2k+rb
                *(unsigned short*)(stg + k*128 + 2048) = lb;
            } else {
                ghf[2*k] = hv;
            }
        }

        // stage x(t+1) into B[p1] x-block (local-only)
        if (t + 1 < SS) {
            unsigned char* dst = smem + BOFF + p1*BPARN + xob;
            const float vv[4] = {xv.x, xv.y, xv.z, xv.w};
            #pragma unroll
            for (int i = 0; i < 4; ++i) {
                unsigned short hb, lb; split1(vv[i], hb, lb);
                *(unsigned short*)(dst + i*64)        = hb;
                *(unsigned short*)(dst + i*64 + 2048) = lb;
            }
        }

        __syncthreads();   // staging complete (local B[p1] rank block + x block)

        if (tid == 0 && t + 1 < SS) {
            // backpressure: every CTA done reading its B[p1] (posted at t-1)
            if (t > 0) mbar_wait(base + MB_EMPTY0 + p1*8, (unsigned)ph);
            fence_pa();    // order generic STS before async-proxy bulk reads
            unsigned src = base + BOFF + p1*BPARN + (unsigned)rank*4096u;
            unsigned fmb = base + MB_FULL0 + p1*8;
            #pragma unroll
            for (unsigned rr = 0; rr < CL; ++rr) {
                if (rr != rank)
                    bulk_s2s(mapa_sh(src, rr), src, 4096u, mapa_sh(fmb, rr));
            }
        }
    }

    csync();   // keep SMEM alive until every peer's posted ops land
}

// ---------------------------------------------------------------------------
// Epilogue: out = h @ W_out^T + b_out, then layernorm over O=24
// ---------------------------------------------------------------------------
__global__ void __launch_bounds__(64) epi_kernel(const float* __restrict__ Wo,
                                                 const float* __restrict__ bo,
                                                 float* __restrict__ out)
{
    __shared__ float hrow[HH];
    __shared__ float ov[OO];
    __shared__ float s_mu, s_rs;
    int b = blockIdx.x, tid = threadIdx.x;

    const float4* hs = (const float4*)(g_hfinal + (size_t)b*HH);
    for (int i = tid; i < HH/4; i += 64) ((float4*)hrow)[i] = hs[i];
    __syncthreads();

    if (tid < OO) {
        float s = bo[tid];
        const float* w = Wo + (size_t)tid*HH;
        #pragma unroll 8
        for (int k = 0; k < HH; ++k) s += hrow[k]*w[k];
        ov[tid] = s;
    }
    __syncthreads();
    if (tid == 0) {
        float mu = 0.f;
        for (int o = 0; o < OO; ++o) mu += ov[o];
        mu *= (1.f/OO);
        float va = 0.f;
        for (int o = 0; o < OO; ++o) { float d = ov[o]-mu; va += d*d; }
        va *= (1.f/OO);
        s_mu = mu; s_rs = rsqrtf(va + 1e-5f);
    }
    __syncthreads();
    if (tid < OO) out[(size_t)b*OO + tid] = (ov[tid]-s_mu)*s_rs;
}

// ---------------------------------------------------------------------------
extern "C" void kernel_launch(void* const* d_in, const int* in_sizes, int n_in,
                              void* d_out, int out_size)
{
    (void)in_sizes; (void)n_in; (void)out_size;
    const float* x     = (const float*)d_in[0];
    const float* W_in  = (const float*)d_in[1];
    const float* b_in  = (const float*)d_in[2];
    const float* W     = (const float*)d_in[3];
    const float* R     = (const float*)d_in[4];
    const float* b     = (const float*)d_in[5];
    const float* W_out = (const float*)d_in[6];
    const float* b_out = (const float*)d_in[7];
    float* out = (float*)d_out;

    cudaFuncSetAttribute(recur_kernel, cudaFuncAttributeMaxDynamicSharedMemorySize, SMEM_BYTES);

    prep_kernel<<<(CL*128*296 + 255)/256, 256>>>(W, R, b, b_in, W_in);  // launch 0
    dummy_kernel<<<1, 32>>>();                                           // launch 1
    dummy_kernel<<<1, 32>>>();                                           // launch 2
    recur_kernel<<<GRID_R, NTHR, SMEM_BYTES>>>(x);                       // launch 3 (ncu)
    epi_kernel<<<BB, 64>>>(W_out, b_out, out);                           // launch 4
}

// round 16
// speedup vs baseline: 1.4478x; 1.4478x over previous
#include <cuda_runtime.h>
#include <cuda_bf16.h>
#include <math.h>

// Problem constants
#define BB    512
#define SS    256
#define IDIM  32
#define HH    256
#define OO    24

// Geometry
#define CL     8                  // CTAs per cluster
#define ROWS   32                 // batch rows per cluster
#define NCLU   (BB/ROWS)          // 16 clusters
#define GRID_R (NCLU*CL)          // 128 CTAs
#define NTHR   256                // 8 warps, all GEMM (n-split: 32m x 16n each)
#define NCH    18                 // 18 k16 chunks (k 0..287)

#define ASTRIDE 592               // A bytes per m-row (576 + 16 pad)
#define A_BYTES (128*ASTRIDE)     // 75776 per precision

// B layout (NEW): [n][k8-group], each group = [16B hi | 16B lo] interleaved.
// 36 groups (k 0..287) = 1152B data + 16 pad = 1168B/row (4-word bank rotation:
// 1168/4 = 292 = 4 mod 32 -> 8 ldmatrix rows hit banks 0,4,..,28: conflict-free)
#define BSTRIDE 1168
#define BPAR2   (32*BSTRIDE)      // 37376 bytes per parity

// SMEM offsets (bytes)
#define A_HI   0
#define A_LO   75776
#define BOFF   151552             // B[p] at BOFF + p*BPAR2
#define SMEM_BYTES (BOFF + 2*BPAR2)   // 226304

// Device scratch
__device__ __align__(16) unsigned char g_Ahi[CL*A_BYTES];
__device__ __align__(16) unsigned char g_Alo[CL*A_BYTES];
__device__ float g_bc[CL*128];    // composed bias [rank][m = c*4+q]
__device__ float g_hfinal[BB*HH];

typedef unsigned long long u64;

// ---------------- helpers ----------------
__device__ __forceinline__ unsigned s2u(const void *p) {
    unsigned r;
    asm("{.reg .u64 t; cvta.to.shared.u64 t,%1; cvt.u32.u64 %0,t;}" : "=r"(r) : "l"(p));
    return r;
}
__device__ __forceinline__ unsigned mapa_sh(unsigned a, unsigned r) {
    unsigned o; asm("mapa.shared::cluster.u32 %0,%1,%2;" : "=r"(o) : "r"(a), "r"(r)); return o;
}
__device__ __forceinline__ void stc128(unsigned a, u64 v0, u64 v1) {
    asm volatile("st.shared::cluster.v2.b64 [%0],{%1,%2};" :: "r"(a), "l"(v0), "l"(v1) : "memory");
}
__device__ __forceinline__ void carr() { asm volatile("barrier.cluster.arrive.aligned;" ::: "memory"); }
__device__ __forceinline__ void cwait(){ asm volatile("barrier.cluster.wait.aligned;"   ::: "memory"); }
__device__ __forceinline__ void csync(){ carr(); cwait(); }

__device__ __forceinline__ void ldm4(unsigned* r, unsigned a) {
    asm volatile("ldmatrix.sync.aligned.m8n8.x4.shared.b16 {%0,%1,%2,%3},[%4];"
        : "=r"(r[0]), "=r"(r[1]), "=r"(r[2]), "=r"(r[3]) : "r"(a));
}
__device__ __forceinline__ void mma16816(float* d, const unsigned* a, unsigned b0, unsigned b1) {
    asm volatile("mma.sync.aligned.m16n8k16.row.col.f32.bf16.bf16.f32 "
        "{%0,%1,%2,%3},{%4,%5,%6,%7},{%8,%9},{%0,%1,%2,%3};"
        : "+f"(d[0]), "+f"(d[1]), "+f"(d[2]), "+f"(d[3])
        : "r"(a[0]), "r"(a[1]), "r"(a[2]), "r"(a[3]), "r"(b0), "r"(b1));
}

__device__ __forceinline__ float fast_tanh(float x) {
    return 1.f - __fdividef(2.f, __expf(2.f*x) + 1.f);
}
__device__ __forceinline__ unsigned prmt(unsigned a, unsigned b, unsigned sel) {
    unsigned r; asm("prmt.b32 %0,%1,%2,%3;" : "=r"(r) : "r"(a), "r"(b), "r"(sel)); return r;
}
__device__ __forceinline__ void split1(float v, unsigned short &h, unsigned short &l) {
    __nv_bfloat16 bh = __float2bfloat16(v);
    h = __bfloat16_as_ushort(bh);
    l = __bfloat16_as_ushort(__float2bfloat16(v - __bfloat162float(bh)));
}

// ---------------------------------------------------------------------------
// prep: bf16 hi/lo weight images [rank][m][k], m = c*4+q <-> gate g = q*256+rank*32+c
// ---------------------------------------------------------------------------
__global__ void prep_kernel(const float* __restrict__ W, const float* __restrict__ R,
                            const float* __restrict__ b, const float* __restrict__ b_in,
                            const float* __restrict__ W_in)
{
    int idx = blockIdx.x * blockDim.x + threadIdx.x;
    if (idx < CL*128*296) {
        int kk   = idx % 296;
        int m    = (idx / 296) % 128;
        int rank = idx / (296*128);
        int c = m >> 2, q = m & 3;
        int g = q*256 + rank*32 + c;
        float w = 0.f;
        if (kk < 256) {
            w = W[(size_t)g*512 + 256 + kk] + R[(size_t)g*256 + kk];
        } else if (kk < 288) {
            int i = kk - 256;
            float s = 0.f;
            for (int h = 0; h < HH; ++h) s += W[(size_t)g*512 + h] * W_in[(size_t)h*IDIM + i];
            w = s;
        }
        __nv_bfloat16 hi = __float2bfloat16(w);
        __nv_bfloat16 lo = __float2bfloat16(w - __bfloat162float(hi));
        size_t off = (size_t)rank*A_BYTES + (size_t)m*ASTRIDE + kk*2;
        *(__nv_bfloat16*)(g_Ahi + off) = hi;
        *(__nv_bfloat16*)(g_Alo + off) = lo;
    }
    if (idx < CL*128) {
        int m = idx & 127, rank = idx >> 7;
        int c = m >> 2, q = m & 3;
        int g = q*256 + rank*32 + c;
        float s = b[g];
        for (int h = 0; h < HH; ++h) s += W[(size_t)g*512 + h] * b_in[h];
        g_bc[idx] = s;
    }
}

__global__ void dummy_kernel() {}

// ---------------------------------------------------------------------------
// Recurrence: R12 structure exactly (8 warps n-split, one csync per step);
// ONLY change: B tile hi/lo-interleaved at 16B so the h broadcast is
// 8 x stc128 per thread (2048 msgs/CTA) instead of 16 x stc64 (4096 msgs).
// ---------------------------------------------------------------------------
__global__ void __cluster_dims__(CL, 1, 1) __launch_bounds__(NTHR, 1)
recur_kernel(const float* __restrict__ x)
{
    extern __shared__ unsigned char smem[];
    const unsigned base = s2u(smem);

    unsigned rank; asm("mov.u32 %0, %%cluster_ctarank;" : "=r"(rank));
    const int cid  = blockIdx.x >> 3;
    const int b0   = cid * ROWS;
    const int tid  = threadIdx.x;
    const int lane = tid & 31;
    const int warp = tid >> 5;
    const int kh   = warp >> 2;    // batch-row half
    const int wm   = warp & 3;     // m-tile

    // ---- load resident A tiles; zero B parity-0 ----
    {
        const float4* sa = (const float4*)(g_Ahi + (size_t)rank*A_BYTES);
        const float4* sb = (const float4*)(g_Alo + (size_t)rank*A_BYTES);
        float4* da = (float4*)(smem + A_HI);
        float4* db = (float4*)(smem + A_LO);
        for (int i = tid; i < A_BYTES/16; i += NTHR) { da[i] = sa[i]; db[i] = sb[i]; }
        float4 z = make_float4(0.f,0.f,0.f,0.f);
        float4* bz = (float4*)(smem + BOFF);
        for (int i = tid; i < BPAR2/16; i += NTHR) bz[i] = z;
    }
    __syncthreads();

    // ---- x staging: n_s = tid>>3, 4 features at f_s (within one k8-group) ----
    const int n_s = tid >> 3;
    const int f_s = (tid & 7) * 4;
    const float* xrb = x + (size_t)(b0 + n_s)*SS*IDIM + f_s;
    // group g = 32 + (f_s>>3); hi at group base + (f_s&7)*2; lo at +16
    const unsigned xob = (unsigned)n_s*BSTRIDE + (unsigned)(32 + (f_s >> 3))*32 + (unsigned)(f_s & 7)*2;

    {   // stage x(0) into parity 0
        float4 a0 = *(const float4*)(xrb);
        const float vv[4] = {a0.x, a0.y, a0.z, a0.w};
        u64 H = 0, L = 0;
        #pragma unroll
        for (int i = 0; i < 4; ++i) {
            unsigned short hb, lb; split1(vv[i], hb, lb);
            H |= (u64)hb << (16*i); L |= (u64)lb << (16*i);
        }
        *(u64*)(smem + BOFF + xob)      = H;
        *(u64*)(smem + BOFF + xob + 16) = L;
    }
    __syncthreads();
    csync();                       // B(0) ready cluster-wide

    // ---- GEMM lane addressing ----
    const unsigned aH  = base + A_HI + (unsigned)(wm*32 + (lane & 15))*ASTRIDE + (lane >> 4)*16;
    const unsigned aL  = aH + (A_LO - A_HI);
    // B: per-lane base covers (n = kh*16 + lane&15, k8-subgroup = lane>>4)
    const unsigned bB  = base + BOFF + (unsigned)(kh*16 + (lane & 15))*BSTRIDE + (unsigned)(lane >> 4)*32;
    const int r   = lane >> 2;     // 0..7
    const int qt  = lane & 3;
    const int s2  = r & 3;
    const int rb  = r >> 2;        // cells at c_local = wm*8 + 2k + rb

    const int n_e = kh*16 + (s2 >> 1)*8 + qt*2 + (s2 & 1);
    float bias[4][4];
    float cst[4], nst[4], mst[4];
    unsigned raH[CL];
    #pragma unroll
    for (int k = 0; k < 4; ++k)
        #pragma unroll
        for (int j = 0; j < 4; ++j)
            bias[j][k] = g_bc[rank*128 + (wm*8 + 2*k + rb)*4 + j];
    #pragma unroll
    for (int u = 0; u < 4; ++u) { cst[u]=0.f; nst[u]=0.f; mst[u]=0.f; }
    {
        // 16B destination: row n_e, k8-group rank*4+wm, hi (rb=0) or lo (rb=1)
        unsigned off = base + BOFF + (unsigned)n_e*BSTRIDE
                     + (unsigned)(rank*4 + wm)*32 + (unsigned)rb*16;
        #pragma unroll
        for (unsigned rr = 0; rr < CL; ++rr) raH[rr] = mapa_sh(off, rr);
    }
    float* ghf = g_hfinal + (size_t)(b0 + n_e)*HH + rank*32 + wm*8 + rb;

    for (int t = 0; t < SS; ++t) {
        const unsigned p  = (unsigned)(t & 1);
        const unsigned p1 = p ^ 1u;

        // prefetch x(t+1)
        float4 xv;
        if (t + 1 < SS) xv = *(const float4*)(xrb + (size_t)(t+1)*IDIM);

        // ---- GEMM: 32m x 16n x 288k, 3-term hi/lo ----
        float d[2][2][4];
        #pragma unroll
        for (int mi = 0; mi < 2; ++mi)
            #pragma unroll
            for (int nj = 0; nj < 2; ++nj)
                #pragma unroll
                for (int e = 0; e < 4; ++e) d[mi][nj][e] = 0.f;

        const unsigned bP = bB + p*BPAR2;
        #pragma unroll 6
        for (int ch = 0; ch < NCH; ++ch) {
            unsigned ka = (unsigned)ch*32;          // A byte offset
            unsigned bo = (unsigned)ch*64;          // B group-pair offset
            unsigned AH0[4], AH1[4], AL0[4], AL1[4], BH[4], BL[4];
            ldm4(AH0, aH + ka); ldm4(AH1, aH + 16*ASTRIDE + ka);
            ldm4(AL0, aL + ka); ldm4(AL1, aL + 16*ASTRIDE + ka);
            ldm4(BH, bP + bo);  ldm4(BL, bP + bo + 16);
            #pragma unroll
            for (int nj = 0; nj < 2; ++nj) {
                mma16816(d[0][nj], AH0, BH[nj], BH[nj+2]);
                mma16816(d[0][nj], AL0, BH[nj], BH[nj+2]);
                mma16816(d[0][nj], AH0, BL[nj], BL[nj+2]);
                mma16816(d[1][nj], AH1, BH[nj], BH[nj+2]);
                mma16816(d[1][nj], AL1, BH[nj], BH[nj+2]);
                mma16816(d[1][nj], AH1, BL[nj], BL[nj+2]);
            }
        }

        // ---- 4x4 transpose: gates (lane bits 2-3) <-> cols (nj,np) ----
        float v[4][4];
        #pragma unroll
        for (int mi = 0; mi < 2; ++mi)
            #pragma unroll
            for (int nj = 0; nj < 2; ++nj)
                #pragma unroll
                for (int e = 0; e < 4; ++e)
                    v[nj*2 + (e & 1)][2*mi + (e >> 1)] = d[mi][nj][e];

        float t1[4][4], g[4][4];
        #pragma unroll
        for (int j = 0; j < 4; ++j) {
            bool sw = ((s2 ^ j) & 1) != 0;
            #pragma unroll
            for (int k = 0; k < 4; ++k) {
                float ov = __shfl_xor_sync(0xffffffffu, v[j^1][k], 4);
                t1[j][k] = sw ? ov : v[j][k];
            }
        }
        #pragma unroll
        for (int j = 0; j < 4; ++j) {
            bool sw = ((s2 ^ j) & 2) != 0;
            #pragma unroll
            for (int k = 0; k < 4; ++k) {
                float ov = __shfl_xor_sync(0xffffffffu, t1[j^2][k], 8);
                g[j][k] = sw ? ov : t1[j][k];
            }
        }
        // g[j][k]: gate j for cell (c_local = wm*8 + 2k+rb, n = n_e)

        // ---- pointwise sLSTM (4 cells) ----
        float hq[4];
        #pragma unroll
        for (int k = 0; k < 4; ++k) {
            float gi = g[0][k] + bias[0][k];
            float gf = g[1][k] + bias[1][k];
            float gz = g[2][k] + bias[2][k];
            float go = g[3][k] + bias[3][k];
            float lf  = -__logf(1.f + __expf(-gf));
            float mn  = fmaxf(lf + mst[k], gi);
            float ipr = __expf(gi - mn);
            float fp  = __expf(lf + mst[k] - mn);
            float cn  = fp*cst[k] + ipr*fast_tanh(gz);
            float nn  = fp*nst[k] + ipr;
            float so  = __fdividef(1.f, 1.f + __expf(-go));
            hq[k] = so * fast_tanh(__fdividef(cn, nn));
            cst[k]=cn; nst[k]=nn; mst[k]=mn;
        }

        // stage x(t+1) into B[p1] x-region (local-only; disjoint from h-region)
        if (t + 1 < SS) {
            const float vv[4] = {xv.x, xv.y, xv.z, xv.w};
            u64 H = 0, L = 0;
            #pragma unroll
            for (int i = 0; i < 4; ++i) {
                unsigned short hb, lb; split1(vv[i], hb, lb);
                H |= (u64)hb << (16*i); L |= (u64)lb << (16*i);
            }
            *(u64*)(smem + BOFF + p1*BPAR2 + xob)      = H;
            *(u64*)(smem + BOFF + p1*BPAR2 + xob + 16) = L;
        }

        // ---- hi/lo split + pair exchange + 8 x stc128 broadcast ----
        if (t + 1 < SS) {
            unsigned short hs[4], ls[4];
            #pragma unroll
            for (int k = 0; k < 4; ++k) split1(hq[k], hs[k], ls[k]);
            u64 hp = (u64)hs[0] | ((u64)hs[1]<<16) | ((u64)hs[2]<<32) | ((u64)hs[3]<<48);
            u64 lp = (u64)ls[0] | ((u64)ls[1]<<16) | ((u64)ls[2]<<32) | ((u64)ls[3]<<48);
            // rb=0 sends lo-pack, receives partner's hi-pack (odd cells' hi);
            // rb=1 sends hi-pack, receives partner's lo-pack (even cells' lo).
            u64 sendv = rb ? hp : lp;
            u64 got = __shfl_xor_sync(0xffffffffu, sendv, 16);
            u64 EV = rb ? got : hp;    // even cells (c = wm*8 + 2k)
            u64 OD = rb ? lp  : got;   // odd  cells (c = wm*8 + 2k+1)
            // interleave 16-bit: group = [v(c0),v(c1),...,v(c7)] of hi (rb=0) / lo (rb=1)
            unsigned a0 = (unsigned)EV, a1 = (unsigned)(EV >> 32);
            unsigned c0 = (unsigned)OD, c1 = (unsigned)(OD >> 32);
            unsigned o00 = prmt(a0, c0, 0x5410), o01 = prmt(a0, c0, 0x7632);
            unsigned o10 = prmt(a1, c1, 0x5410), o11 = prmt(a1, c1, 0x7632);
            u64 v0 = (u64)o00 | ((u64)o01 << 32);
            u64 v1 = (u64)o10 | ((u64)o11 << 32);
            unsigned add = p1*BPAR2;
            #pragma unroll
            for (unsigned rr = 0; rr < CL; ++rr)
                stc128(raH[rr] + add, v0, v1);
        } else {
            // final step: store own 4 cells (stride-2 in hid) to GMEM
            #pragma unroll
            for (int k = 0; k < 4; ++k) ghf[2*k] = hq[k];
        }

        if (t + 1 < SS) csync();   // release writes to B[p1]; acquire everyone's
    }
}

// ---------------------------------------------------------------------------
// Epilogue: out = h @ W_out^T + b_out, then layernorm over O=24
// ---------------------------------------------------------------------------
__global__ void __launch_bounds__(64) epi_kernel(const float* __restrict__ Wo,
                                                 const float* __restrict__ bo,
                                                 float* __restrict__ out)
{
    __shared__ float hrow[HH];
    __shared__ float ov[OO];
    __shared__ float s_mu, s_rs;
    int b = blockIdx.x, tid = threadIdx.x;

    const float4* hs = (const float4*)(g_hfinal + (size_t)b*HH);
    for (int i = tid; i < HH/4; i += 64) ((float4*)hrow)[i] = hs[i];
    __syncthreads();

    if (tid < OO) {
        float s = bo[tid];
        const float* w = Wo + (size_t)tid*HH;
        #pragma unroll 8
        for (int k = 0; k < HH; ++k) s += hrow[k]*w[k];
        ov[tid] = s;
    }
    __syncthreads();
    if (tid == 0) {
        float mu = 0.f;
        for (int o = 0; o < OO; ++o) mu += ov[o];
        mu *= (1.f/OO);
        float va = 0.f;
        for (int o = 0; o < OO; ++o) { float d = ov[o]-mu; va += d*d; }
        va *= (1.f/OO);
        s_mu = mu; s_rs = rsqrtf(va + 1e-5f);
    }
    __syncthreads();
    if (tid < OO) out[(size_t)b*OO + tid] = (ov[tid]-s_mu)*s_rs;
}

// ---------------------------------------------------------------------------
extern "C" void kernel_launch(void* const* d_in, const int* in_sizes, int n_in,
                              void* d_out, int out_size)
{
    (void)in_sizes; (void)n_in; (void)out_size;
    const float* x     = (const float*)d_in[0];
    const float* W_in  = (const float*)d_in[1];
    const float* b_in  = (const float*)d_in[2];
    const float* W     = (const float*)d_in[3];
    const float* R     = (const float*)d_in[4];
    const float* b     = (const float*)d_in[5];
    const float* W_out = (const float*)d_in[6];
    const float* b_out = (const float*)d_in[7];
    float* out = (float*)d_out;

    cudaFuncSetAttribute(recur_kernel, cudaFuncAttributeMaxDynamicSharedMemorySize, SMEM_BYTES);

    prep_kernel<<<(CL*128*296 + 255)/256, 256>>>(W, R, b, b_in, W_in);  // launch 0
    dummy_kernel<<<1, 32>>>();                                           // launch 1
    dummy_kernel<<<1, 32>>>();                                           // launch 2
    recur_kernel<<<GRID_R, NTHR, SMEM_BYTES>>>(x);                       // launch 3 (ncu)
    epi_kernel<<<BB, 64>>>(W_out, b_out, out);                           // launch 4
}